// round 8
// baseline (speedup 1.0000x reference)
#include <cuda_runtime.h>
#include <cuda_bf16.h>
#include <cstdint>

#define NN   50000
#define EE   800000
#define FIN  128
#define H1   8
#define C1   32
#define HC   256
#define CO   10
#define NG   128
#define NEG_SLOPE 0.2f
#define NBLK 196          // ceil(NN/256)

// ---------------- scratch ----------------------------------------------------
__device__ __nv_bfloat16  g_xhb[(size_t)NN * HC];
__device__ __nv_bfloat16  g_h1b[(size_t)NN * HC];
__device__ __nv_bfloat16  g_w1b[(size_t)HC * FIN];
__device__ float g_as1[NN * H1];
__device__ float g_ad1[NN * H1];
__device__ int   g_deg[NN];
__device__ int   g_off[NN + 1];
__device__ int   g_cur[NN];
__device__ int   g_part[NBLK];
__device__ int   g_ssrc[EE];
__device__ float g_xh2[(size_t)NN * 16];
__device__ float g_as2[NN];
__device__ float g_ad2[NN];
__device__ float g_sums[NG * CO];
__device__ float g_cnt[NG];

__device__ __forceinline__ float lrelu(float x) {
    return fmaxf(x, 0.0f) + NEG_SLOPE * fminf(x, 0.0f);
}
__device__ __forceinline__ float elu(float x) {
    return x > 0.0f ? x : (__expf(x) - 1.0f);
}
__device__ __forceinline__ void mma16816(float* d, const uint32_t* a, const uint32_t* b) {
    asm volatile(
        "mma.sync.aligned.m16n8k16.row.col.f32.bf16.bf16.f32 "
        "{%0,%1,%2,%3}, {%4,%5,%6,%7}, {%8,%9}, {%0,%1,%2,%3};"
        : "+f"(d[0]), "+f"(d[1]), "+f"(d[2]), "+f"(d[3])
        : "r"(a[0]), "r"(a[1]), "r"(a[2]), "r"(a[3]), "r"(b[0]), "r"(b[1]));
}
__device__ __forceinline__ void ldsm4(uint32_t& r0, uint32_t& r1, uint32_t& r2,
                                      uint32_t& r3, uint32_t addr) {
    asm volatile("ldmatrix.sync.aligned.m8n8.x4.shared.b16 {%0,%1,%2,%3}, [%4];"
                 : "=r"(r0), "=r"(r1), "=r"(r2), "=r"(r3) : "r"(addr));
}
// swizzled offset for 256B rows (128 bf16): 16B chunk c16 in row r
__device__ __forceinline__ uint32_t swz(int r, int c16) {
    return (uint32_t)(r * 256 + (c16 >> 3) * 128 + (((c16 & 7) ^ (r & 7)) << 4));
}

// ---------------- 0. zero ----------------------------------------------------
__global__ void k_zero() {
    int i = blockIdx.x * blockDim.x + threadIdx.x;
    if (i < NN) g_deg[i] = 0;
    if (i < NG * CO) g_sums[i] = 0.0f;
    if (i < NG) g_cnt[i] = 0.0f;
}

// ---------------- W1 transpose+convert ----------------------------------------
__global__ void k_cvt_w(const float* __restrict__ W1) {
    __shared__ float s[32][33];
    int k0 = blockIdx.x * 32;
    int n0 = blockIdx.y * 32;
    int tx = threadIdx.x, ty = threadIdx.y;
    s[ty][tx] = W1[(size_t)(k0 + ty) * HC + n0 + tx];
    __syncthreads();
    g_w1b[(size_t)(n0 + ty) * FIN + k0 + tx] = __float2bfloat16(s[tx][ty]);
}

// ---------------- GEMM1 HMMA: CTA tile 32x256, K=128, 3 CTAs/SM ----------------
// smem: A 32x128 bf16 swizzled (8KB) + B 256x128 bf16 swizzled (64KB)
#define G1_ASZ  8192
#define G1_SMEM (G1_ASZ + 65536)
__global__ void __launch_bounds__(256, 3) k_gemm1(const float* __restrict__ x,
                                                  const float* __restrict__ att_src,
                                                  const float* __restrict__ att_dst) {
    extern __shared__ char smem[];
    char* sA = smem;
    char* sB = smem + G1_ASZ;
    const int tid = threadIdx.x;
    const int wid = tid >> 5;
    const int lane = tid & 31;
    const int bm = blockIdx.x * 32;
    const int mw = wid >> 2;          // 0..1
    const int nw = wid & 3;           // 0..3
    const int g = lane >> 2;
    const int t2 = (lane & 3) * 2;

    // ---- load A: 32 rows x 128 bf16, 512 chunks of 16B, 2 per thread ----
#pragma unroll
    for (int i = 0; i < 2; i++) {
        int chunk = tid + i * 256;
        int r = chunk >> 4;
        int c16 = chunk & 15;
        int grow = bm + r;
        float4 v0 = make_float4(0.f, 0.f, 0.f, 0.f), v1 = v0;
        if (grow < NN) {
            const float4* p = (const float4*)(x + (size_t)grow * FIN + c16 * 8);
            v0 = p[0]; v1 = p[1];
        }
        __nv_bfloat162 b[4];
        b[0] = __floats2bfloat162_rn(v0.x, v0.y);
        b[1] = __floats2bfloat162_rn(v0.z, v0.w);
        b[2] = __floats2bfloat162_rn(v1.x, v1.y);
        b[3] = __floats2bfloat162_rn(v1.z, v1.w);
        *(uint4*)(sA + swz(r, c16)) = *(uint4*)b;
    }
    // ---- load B: 256 rows x 128 bf16, 4096 chunks, 16 per thread ----
#pragma unroll
    for (int i = 0; i < 16; i++) {
        int chunk = tid + i * 256;
        int r = chunk >> 4;
        int c16 = chunk & 15;
        uint4 v = *(const uint4*)(g_w1b + (size_t)r * FIN + c16 * 8);
        *(uint4*)(sB + swz(r, c16)) = v;
    }
    __syncthreads();

    const uint32_t sAu = (uint32_t)__cvta_generic_to_shared(sA);
    const uint32_t sBu = (uint32_t)__cvta_generic_to_shared(sB);
    const int arow = mw * 16 + (lane & 15);
    const int ahi = (lane >> 4) & 1;
    const int brow0 = nw * 64 + (lane & 7) + ((lane >> 4) & 1) * 8;
    const int bhi = (lane >> 3) & 1;

    float acc[8][4];
#pragma unroll
    for (int j = 0; j < 8; j++)
#pragma unroll
        for (int q = 0; q < 4; q++) acc[j][q] = 0.f;

#pragma unroll
    for (int kk = 0; kk < 8; kk++) {
        uint32_t afr[4];
        ldsm4(afr[0], afr[1], afr[2], afr[3], sAu + swz(arow, kk * 2 + ahi));
        uint32_t bfr[8][2];
#pragma unroll
        for (int jp = 0; jp < 4; jp++) {
            ldsm4(bfr[2 * jp][0], bfr[2 * jp][1], bfr[2 * jp + 1][0], bfr[2 * jp + 1][1],
                  sBu + swz(brow0 + jp * 16, kk * 2 + bhi));
        }
#pragma unroll
        for (int j = 0; j < 8; j++) mma16816(acc[j], afr, bfr[j]);
    }

    // ---- fused epilogue ----
    const int r0 = bm + mw * 16 + g;
    const int r1 = r0 + 8;
#pragma unroll
    for (int j = 0; j < 8; j++) {
        const int c = nw * 64 + j * 8 + t2;
        __nv_bfloat162 v0 = __floats2bfloat162_rn(acc[j][0], acc[j][1]);
        __nv_bfloat162 v1 = __floats2bfloat162_rn(acc[j][2], acc[j][3]);
        if (r0 < NN) *(uint32_t*)(g_xhb + (size_t)r0 * HC + c) = *(uint32_t*)&v0;
        if (r1 < NN) *(uint32_t*)(g_xhb + (size_t)r1 * HC + c) = *(uint32_t*)&v1;
    }
#pragma unroll
    for (int hh = 0; hh < 2; hh++) {
        float ps0 = 0.f, pd0 = 0.f, ps1 = 0.f, pd1 = 0.f;
#pragma unroll
        for (int jj = 0; jj < 4; jj++) {
            const int j = hh * 4 + jj;
            const int c = nw * 64 + j * 8 + t2;
            float2 s2 = *(const float2*)(att_src + c);
            float2 d2 = *(const float2*)(att_dst + c);
            ps0 = fmaf(acc[j][0], s2.x, fmaf(acc[j][1], s2.y, ps0));
            pd0 = fmaf(acc[j][0], d2.x, fmaf(acc[j][1], d2.y, pd0));
            ps1 = fmaf(acc[j][2], s2.x, fmaf(acc[j][3], s2.y, ps1));
            pd1 = fmaf(acc[j][2], d2.x, fmaf(acc[j][3], d2.y, pd1));
        }
        ps0 += __shfl_xor_sync(0xffffffffu, ps0, 1);
        pd0 += __shfl_xor_sync(0xffffffffu, pd0, 1);
        ps1 += __shfl_xor_sync(0xffffffffu, ps1, 1);
        pd1 += __shfl_xor_sync(0xffffffffu, pd1, 1);
        ps0 += __shfl_xor_sync(0xffffffffu, ps0, 2);
        pd0 += __shfl_xor_sync(0xffffffffu, pd0, 2);
        ps1 += __shfl_xor_sync(0xffffffffu, ps1, 2);
        pd1 += __shfl_xor_sync(0xffffffffu, pd1, 2);
        const int h = nw * 2 + hh;
        if ((lane & 3) == 0) {
            if (r0 < NN) { g_as1[r0 * H1 + h] = ps0; g_ad1[r0 * H1 + h] = pd0; }
            if (r1 < NN) { g_as1[r1 * H1 + h] = ps1; g_ad1[r1 * H1 + h] = pd1; }
        }
    }
}

// ---------------- CSR build ----------------------------------------------------
__global__ void k_hist(const int* __restrict__ ei, int E) {
    int e = blockIdx.x * blockDim.x + threadIdx.x;
    if (e < E) atomicAdd(&g_deg[ei[E + e]], 1);
}
__global__ void k_scan1() {
    __shared__ int s[256];
    int i = blockIdx.x * 256 + threadIdx.x;
    int v = (i < NN) ? g_deg[i] : 0;
    s[threadIdx.x] = v;
    __syncthreads();
    for (int o = 128; o; o >>= 1) {
        if (threadIdx.x < o) s[threadIdx.x] += s[threadIdx.x + o];
        __syncthreads();
    }
    if (threadIdx.x == 0) g_part[blockIdx.x] = s[0];
}
__global__ void k_scan2() {
    __shared__ int s[256];
    int t = threadIdx.x;
    int v = (t < NBLK) ? g_part[t] : 0;
    s[t] = v;
    __syncthreads();
    for (int o = 1; o < 256; o <<= 1) {
        int u = (t >= o) ? s[t - o] : 0;
        __syncthreads();
        s[t] += u;
        __syncthreads();
    }
    if (t < NBLK) g_part[t] = s[t] - v;
}
__global__ void k_scan3() {
    __shared__ int s[256];
    int t = threadIdx.x;
    int i = blockIdx.x * 256 + t;
    int v = (i < NN) ? g_deg[i] : 0;
    s[t] = v;
    __syncthreads();
    for (int o = 1; o < 256; o <<= 1) {
        int u = (t >= o) ? s[t - o] : 0;
        __syncthreads();
        s[t] += u;
        __syncthreads();
    }
    int base = g_part[blockIdx.x];
    if (i < NN) {
        int off = base + s[t] - v;
        g_off[i] = off;
        g_cur[i] = off;
        if (i == NN - 1) g_off[NN] = base + s[t];
    }
}
__global__ void k_scatter(const int* __restrict__ ei, int E) {
    int e = blockIdx.x * blockDim.x + threadIdx.x;
    if (e < E) {
        int d = ei[E + e];
        int p = atomicAdd(&g_cur[d], 1);
        g_ssrc[p] = ei[e];
    }
}

// ---------------- layer-1 aggregation: warp per node, unroll 4 ------------------
__global__ void k_agg1(const float* __restrict__ b1) {
    const int warp = threadIdx.x >> 5;
    const int lane = threadIdx.x & 31;
    const int n = blockIdx.x * 8 + warp;
    if (n >= NN) return;
    const int h = lane >> 2;
    const int q = lane & 3;
    const int vidx = h * 4 + q;
    const uint4* xb = (const uint4*)g_xhb;

    const float ad = g_ad1[n * H1 + h];
    float w = __expf(lrelu(g_as1[n * H1 + h] + ad));
    float wsum = w;
    float acc[8];
    {
        uint4 sv = xb[(size_t)n * 32 + vidx];
        const __nv_bfloat162* bp = (const __nv_bfloat162*)&sv;
#pragma unroll
        for (int j = 0; j < 4; j++) {
            float2 f = __bfloat1622float2(bp[j]);
            acc[2 * j] = w * f.x;
            acc[2 * j + 1] = w * f.y;
        }
    }
    int e = g_off[n];
    const int end = g_off[n + 1];
    for (; e + 4 <= end; e += 4) {
        const int s0 = g_ssrc[e];
        const int s1 = g_ssrc[e + 1];
        const int s2 = g_ssrc[e + 2];
        const int s3 = g_ssrc[e + 3];
        const float a0 = g_as1[s0 * H1 + h];
        const float a1 = g_as1[s1 * H1 + h];
        const float a2 = g_as1[s2 * H1 + h];
        const float a3 = g_as1[s3 * H1 + h];
        const uint4 v0 = xb[(size_t)s0 * 32 + vidx];
        const uint4 v1 = xb[(size_t)s1 * 32 + vidx];
        const uint4 v2 = xb[(size_t)s2 * 32 + vidx];
        const uint4 v3 = xb[(size_t)s3 * 32 + vidx];
        const float w0 = __expf(lrelu(a0 + ad));
        const float w1 = __expf(lrelu(a1 + ad));
        const float w2 = __expf(lrelu(a2 + ad));
        const float w3 = __expf(lrelu(a3 + ad));
        wsum += (w0 + w1) + (w2 + w3);
        const __nv_bfloat162* p0 = (const __nv_bfloat162*)&v0;
        const __nv_bfloat162* p1 = (const __nv_bfloat162*)&v1;
        const __nv_bfloat162* p2 = (const __nv_bfloat162*)&v2;
        const __nv_bfloat162* p3 = (const __nv_bfloat162*)&v3;
#pragma unroll
        for (int j = 0; j < 4; j++) {
            float2 f0 = __bfloat1622float2(p0[j]);
            float2 f1 = __bfloat1622float2(p1[j]);
            float2 f2 = __bfloat1622float2(p2[j]);
            float2 f3 = __bfloat1622float2(p3[j]);
            acc[2 * j]     = fmaf(w0, f0.x, fmaf(w1, f1.x, fmaf(w2, f2.x, fmaf(w3, f3.x, acc[2 * j]))));
            acc[2 * j + 1] = fmaf(w0, f0.y, fmaf(w1, f1.y, fmaf(w2, f2.y, fmaf(w3, f3.y, acc[2 * j + 1]))));
        }
    }
    for (; e < end; e++) {
        const int s0 = g_ssrc[e];
        const float a0 = g_as1[s0 * H1 + h];
        const uint4 v0 = xb[(size_t)s0 * 32 + vidx];
        const float w0 = __expf(lrelu(a0 + ad));
        wsum += w0;
        const __nv_bfloat162* p0 = (const __nv_bfloat162*)&v0;
#pragma unroll
        for (int j = 0; j < 4; j++) {
            float2 f0 = __bfloat1622float2(p0[j]);
            acc[2 * j]     = fmaf(w0, f0.x, acc[2 * j]);
            acc[2 * j + 1] = fmaf(w0, f0.y, acc[2 * j + 1]);
        }
    }
    const float inv = 1.0f / wsum;
    const int c0 = h * C1 + q * 8;
    __nv_bfloat162 ob[4];
#pragma unroll
    for (int j = 0; j < 4; j++) {
        float ox = elu(acc[2 * j] * inv + b1[c0 + 2 * j]);
        float oy = elu(acc[2 * j + 1] * inv + b1[c0 + 2 * j + 1]);
        ob[j] = __floats2bfloat162_rn(ox, oy);
    }
    ((uint4*)g_h1b)[(size_t)n * 32 + vidx] = *(uint4*)ob;
}

// ---------------- GEMM2 HMMA: 128x16x256, fused attention epilogue --------------
#define G2_ST   264
#define G2_ASZ  (128 * G2_ST * 2)
#define G2_BSZ  (16 * G2_ST * 2)
#define G2_SMEM (G2_ASZ + G2_BSZ)
__global__ void __launch_bounds__(256, 2) k_gemm2(const float* __restrict__ W2,
                                                  const float* __restrict__ att_src2,
                                                  const float* __restrict__ att_dst2) {
    extern __shared__ char smem[];
    char* sA = smem;
    char* sB = smem + G2_ASZ;
    const int tid = threadIdx.x;
    const int wid = tid >> 5;
    const int lane = tid & 31;
    const int bm = blockIdx.x * 128;
    const int g = lane >> 2;
    const int t2 = (lane & 3) * 2;

    for (int i = tid; i < G2_BSZ / 4; i += 256) ((uint32_t*)sB)[i] = 0;
#pragma unroll
    for (int i = 0; i < 16; i++) {
        int idx = tid + i * 256;
        int row = idx >> 5;
        int c16 = idx & 31;
        int grow = bm + row;
        uint4 v = make_uint4(0, 0, 0, 0);
        if (grow < NN) v = *(const uint4*)(g_h1b + (size_t)grow * HC + c16 * 8);
        *(uint4*)(sA + row * (G2_ST * 2) + c16 * 16) = v;
    }
    __syncthreads();
    for (int idx = tid; idx < HC * CO; idx += 256) {
        int k = idx / CO;
        int n = idx % CO;
        ((__nv_bfloat16*)sB)[n * G2_ST + k] = __float2bfloat16(W2[idx]);
    }
    __syncthreads();

    float a0c[4] = {0.f, 0.f, 0.f, 0.f};
    float a1c[4] = {0.f, 0.f, 0.f, 0.f};
#pragma unroll
    for (int kk = 0; kk < 16; kk++) {
        const int k0 = kk * 16;
        const int rb = wid * 16;
        uint32_t afr[4];
        afr[0] = *(const uint32_t*)(sA + (rb + g) * (G2_ST * 2) + (k0 + t2) * 2);
        afr[1] = *(const uint32_t*)(sA + (rb + g + 8) * (G2_ST * 2) + (k0 + t2) * 2);
        afr[2] = *(const uint32_t*)(sA + (rb + g) * (G2_ST * 2) + (k0 + 8 + t2) * 2);
        afr[3] = *(const uint32_t*)(sA + (rb + g + 8) * (G2_ST * 2) + (k0 + 8 + t2) * 2);
        uint32_t b0[2], b1[2];
        b0[0] = *(const uint32_t*)(sB + g * (G2_ST * 2) + (k0 + t2) * 2);
        b0[1] = *(const uint32_t*)(sB + g * (G2_ST * 2) + (k0 + 8 + t2) * 2);
        b1[0] = *(const uint32_t*)(sB + (8 + g) * (G2_ST * 2) + (k0 + t2) * 2);
        b1[1] = *(const uint32_t*)(sB + (8 + g) * (G2_ST * 2) + (k0 + 8 + t2) * 2);
        mma16816(a0c, afr, b0);
        mma16816(a1c, afr, b1);
    }

    const int r0 = bm + wid * 16 + g;
    const int r1 = r0 + 8;
    if (r0 < NN) {
        *(float2*)(g_xh2 + (size_t)r0 * 16 + t2) = make_float2(a0c[0], a0c[1]);
        *(float2*)(g_xh2 + (size_t)r0 * 16 + 8 + t2) = make_float2(a1c[0], a1c[1]);
    }
    if (r1 < NN) {
        *(float2*)(g_xh2 + (size_t)r1 * 16 + t2) = make_float2(a0c[2], a0c[3]);
        *(float2*)(g_xh2 + (size_t)r1 * 16 + 8 + t2) = make_float2(a1c[2], a1c[3]);
    }
    float s0x = att_src2[t2], s0y = att_src2[t2 + 1];
    float d0x = att_dst2[t2], d0y = att_dst2[t2 + 1];
    float s1x = 0.f, s1y = 0.f, d1x = 0.f, d1y = 0.f;
    if (t2 == 0) { s1x = att_src2[8]; s1y = att_src2[9]; d1x = att_dst2[8]; d1y = att_dst2[9]; }
    float ps0 = a0c[0] * s0x + a0c[1] * s0y + a1c[0] * s1x + a1c[1] * s1y;
    float pd0 = a0c[0] * d0x + a0c[1] * d0y + a1c[0] * d1x + a1c[1] * d1y;
    float ps1 = a0c[2] * s0x + a0c[3] * s0y + a1c[2] * s1x + a1c[3] * s1y;
    float pd1 = a0c[2] * d0x + a0c[3] * d0y + a1c[2] * d1x + a1c[3] * d1y;
    ps0 += __shfl_xor_sync(0xffffffffu, ps0, 1);
    pd0 += __shfl_xor_sync(0xffffffffu, pd0, 1);
    ps1 += __shfl_xor_sync(0xffffffffu, ps1, 1);
    pd1 += __shfl_xor_sync(0xffffffffu, pd1, 1);
    ps0 += __shfl_xor_sync(0xffffffffu, ps0, 2);
    pd0 += __shfl_xor_sync(0xffffffffu, pd0, 2);
    ps1 += __shfl_xor_sync(0xffffffffu, ps1, 2);
    pd1 += __shfl_xor_sync(0xffffffffu, pd1, 2);
    if ((lane & 3) == 0) {
        if (r0 < NN) { g_as2[r0] = ps0; g_ad2[r0] = pd0; }
        if (r1 < NN) { g_as2[r1] = ps1; g_ad2[r1] = pd1; }
    }
}

// ---------------- layer-2 aggregation ---------------------------------------------
__global__ void k_agg2(const int* __restrict__ batch, const float* __restrict__ b2) {
    int warp = threadIdx.x >> 5;
    int lane = threadIdx.x & 31;
    int n = blockIdx.x * 8 + warp;
    if (n >= NN) return;
    const int half = lane >> 4;
    const int i = lane & 15;
    const float ad = g_ad2[n];
    float wsum = 0.f, acc = 0.f;
    if (half == 0) {
        float w = __expf(lrelu(g_as2[n] + ad));
        wsum = w;
        acc = w * g_xh2[(size_t)n * 16 + i];
    }
    const int beg = g_off[n], end = g_off[n + 1];
    for (int e = beg + half; e < end; e += 2) {
        const int s = g_ssrc[e];
        const float we = __expf(lrelu(g_as2[s] + ad));
        wsum += we;
        acc = fmaf(we, g_xh2[(size_t)s * 16 + i], acc);
    }
    wsum += __shfl_xor_sync(0xffffffffu, wsum, 16);
    acc += __shfl_xor_sync(0xffffffffu, acc, 16);
    if (half == 0 && i < CO) {
        float out = elu(acc / wsum + b2[i]);
        atomicAdd(&g_sums[batch[n] * CO + i], out);
    }
    if (lane == 0) atomicAdd(&g_cnt[batch[n]], 1.0f);
}

// ---------------- mean + log_softmax ----------------------------------------------
__global__ void k_final(float* __restrict__ out) {
    int g = threadIdx.x;
    if (g >= NG) return;
    float inv = 1.0f / fmaxf(g_cnt[g], 1.0f);
    float v[CO];
    float mx = -1e30f;
#pragma unroll
    for (int c = 0; c < CO; c++) {
        v[c] = g_sums[g * CO + c] * inv;
        mx = fmaxf(mx, v[c]);
    }
    float s = 0.f;
#pragma unroll
    for (int c = 0; c < CO; c++) s += __expf(v[c] - mx);
    float lse = logf(s) + mx;
#pragma unroll
    for (int c = 0; c < CO; c++) out[g * CO + c] = v[c] - lse;
}

// ---------------- launcher ----------------------------------------------------------
extern "C" void kernel_launch(void* const* d_in, const int* in_sizes, int n_in,
                              void* d_out, int out_size) {
    const float* x        = (const float*)d_in[0];
    const int*   ei       = (const int*)d_in[1];
    const int*   batch    = (const int*)d_in[2];
    const float* W1       = (const float*)d_in[3];
    const float* att_src1 = (const float*)d_in[4];
    const float* att_dst1 = (const float*)d_in[5];
    const float* b1       = (const float*)d_in[6];
    const float* W2       = (const float*)d_in[7];
    const float* att_src2 = (const float*)d_in[8];
    const float* att_dst2 = (const float*)d_in[9];
    const float* b2       = (const float*)d_in[10];
    float* out = (float*)d_out;
    const int E = in_sizes[1] / 2;

    static cudaStream_t s1 = nullptr;
    static cudaEvent_t e0 = nullptr, e1 = nullptr;
    if (!s1) {
        cudaStreamCreateWithFlags(&s1, cudaStreamNonBlocking);
        cudaEventCreateWithFlags(&e0, cudaEventDisableTiming);
        cudaEventCreateWithFlags(&e1, cudaEventDisableTiming);
        cudaFuncSetAttribute(k_gemm1, cudaFuncAttributeMaxDynamicSharedMemorySize, G1_SMEM);
        cudaFuncSetAttribute(k_gemm2, cudaFuncAttributeMaxDynamicSharedMemorySize, G2_SMEM);
    }

    cudaEventRecord(e0, 0);
    k_zero<<<(NN + 255) / 256, 256>>>();
    k_hist<<<(E + 255) / 256, 256>>>(ei, E);
    cudaStreamWaitEvent(s1, e0, 0);
    k_cvt_w<<<dim3(FIN / 32, HC / 32), dim3(32, 32), 0, s1>>>(W1);
    k_gemm1<<<(NN + 31) / 32, 256, G1_SMEM, s1>>>(x, att_src1, att_dst1);  // 4th launch (profiled)
    cudaEventRecord(e1, s1);
    k_scan1<<<NBLK, 256>>>();
    k_scan2<<<1, 256>>>();
    k_scan3<<<NBLK, 256>>>();
    k_scatter<<<(E + 255) / 256, 256>>>(ei, E);
    cudaStreamWaitEvent(0, e1, 0);
    k_agg1<<<(NN + 7) / 8, 256>>>(b1);
    k_gemm2<<<(NN + 127) / 128, 256, G2_SMEM>>>(W2, att_src2, att_dst2);
    k_agg2<<<(NN + 7) / 8, 256>>>(batch, b2);
    k_final<<<1, NG>>>(out);
}